// round 2
// baseline (speedup 1.0000x reference)
#include <cuda_runtime.h>
#include <cstdint>

// Problem constants
#define T_TOK   32768        // 8*64*64 tokens
#define DIM     768
#define DIM3    2304
#define HEADS   12
#define HD      64

// Scratch: QKV for one pass (reused), and the out_h+out_w accumulator.
__device__ float g_qkv[(size_t)T_TOK * DIM3];   // 302 MB
__device__ float g_sum[(size_t)T_TOK * DIM];    // 100 MB

// ---------------------------------------------------------------------------
// SGEMM with bias: C[M,N] = A[M,K] @ B[K,N] + bias[N]
// BM=BN=128, BK=16, 256 threads, 8x8 register micro-tile per thread.
// ---------------------------------------------------------------------------
#define BM 128
#define BN 128
#define BK 16

__global__ __launch_bounds__(256) void sgemm_bias(
    const float* __restrict__ A, const float* __restrict__ B,
    const float* __restrict__ bias, float* __restrict__ C,
    int M, int N, int K)
{
    __shared__ float As[BK][BM + 4];   // A tile stored transposed
    __shared__ float Bs[BK][BN];

    const int tid = threadIdx.x;
    const int tx = tid & 15;           // 0..15 -> N direction
    const int ty = tid >> 4;           // 0..15 -> M direction
    const int row0 = blockIdx.y * BM;
    const int col0 = blockIdx.x * BN;

    const int a_r = tid >> 2;          // 0..63  (rows a_r, a_r+64)
    const int a_c = (tid & 3) * 4;     // 0,4,8,12
    const int b_r = tid >> 5;          // 0..7   (rows b_r, b_r+8)
    const int b_c = (tid & 31) * 4;    // 0..124

    float acc[8][8];
    #pragma unroll
    for (int i = 0; i < 8; i++)
        #pragma unroll
        for (int j = 0; j < 8; j++) acc[i][j] = 0.0f;

    for (int k0 = 0; k0 < K; k0 += BK) {
        #pragma unroll
        for (int h = 0; h < 2; h++) {
            int r = a_r + h * 64;
            float4 v = *(const float4*)(A + (size_t)(row0 + r) * K + k0 + a_c);
            As[a_c + 0][r] = v.x;
            As[a_c + 1][r] = v.y;
            As[a_c + 2][r] = v.z;
            As[a_c + 3][r] = v.w;
        }
        #pragma unroll
        for (int h = 0; h < 2; h++) {
            int r = b_r + h * 8;
            float4 v = *(const float4*)(B + (size_t)(k0 + r) * N + col0 + b_c);
            *(float4*)&Bs[r][b_c] = v;
        }
        __syncthreads();

        #pragma unroll
        for (int kk = 0; kk < BK; kk++) {
            float a[8], b[8];
            float4 a0 = *(const float4*)&As[kk][ty * 8];
            float4 a1 = *(const float4*)&As[kk][ty * 8 + 4];
            float4 b0 = *(const float4*)&Bs[kk][tx * 8];
            float4 b1 = *(const float4*)&Bs[kk][tx * 8 + 4];
            a[0]=a0.x; a[1]=a0.y; a[2]=a0.z; a[3]=a0.w;
            a[4]=a1.x; a[5]=a1.y; a[6]=a1.z; a[7]=a1.w;
            b[0]=b0.x; b[1]=b0.y; b[2]=b0.z; b[3]=b0.w;
            b[4]=b1.x; b[5]=b1.y; b[6]=b1.z; b[7]=b1.w;
            #pragma unroll
            for (int i = 0; i < 8; i++)
                #pragma unroll
                for (int j = 0; j < 8; j++)
                    acc[i][j] = fmaf(a[i], b[j], acc[i][j]);
        }
        __syncthreads();
    }

    #pragma unroll
    for (int i = 0; i < 8; i++) {
        size_t r = (size_t)(row0 + ty * 8 + i);
        #pragma unroll
        for (int j = 0; j < 8; j += 4) {
            int c = col0 + tx * 8 + j;
            float4 v;
            v.x = acc[i][j + 0] + bias[c + 0];
            v.y = acc[i][j + 1] + bias[c + 1];
            v.z = acc[i][j + 2] + bias[c + 2];
            v.w = acc[i][j + 3] + bias[c + 3];
            *(float4*)(C + r * N + c) = v;
        }
    }
}

// ---------------------------------------------------------------------------
// Head-mixing attention, per token (the reference einsum contracts over d
// with l shared: attention is across the 12 HEADS at each position).
//
// One warp per token. Lane l holds d-slices {l, l+32} of k, v, o in regs.
// S[h][g] = scale * dot(q[h], k[g]) via 2 partial FMA + butterfly reduce;
// softmax over g computed redundantly in every lane; o accumulated in regs.
// accumulate=0: out = O ; =1: out += O.
// ---------------------------------------------------------------------------
__global__ __launch_bounds__(256) void head_attn(
    const float* __restrict__ qkv, float* __restrict__ out, int accumulate)
{
    const int lane = threadIdx.x & 31;
    const int warp = threadIdx.x >> 5;
    const int tok  = blockIdx.x * 8 + warp;
    const float* row = qkv + (size_t)tok * DIM3;
    const float scale = 0.125f;        // (768/12)^-0.5

    float k[HEADS][2], v[HEADS][2], o[HEADS][2];
    #pragma unroll
    for (int g = 0; g < HEADS; g++) {
        k[g][0] = row[DIM     + g * HD + lane];
        k[g][1] = row[DIM     + g * HD + lane + 32];
        v[g][0] = row[2 * DIM + g * HD + lane];
        v[g][1] = row[2 * DIM + g * HD + lane + 32];
        o[g][0] = 0.0f;
        o[g][1] = 0.0f;
    }

    #pragma unroll
    for (int h = 0; h < HEADS; h++) {
        float q0 = row[h * HD + lane]      * scale;
        float q1 = row[h * HD + lane + 32] * scale;

        float s[HEADS];
        #pragma unroll
        for (int g = 0; g < HEADS; g++)
            s[g] = fmaf(q0, k[g][0], q1 * k[g][1]);

        #pragma unroll
        for (int off = 16; off > 0; off >>= 1)
            #pragma unroll
            for (int g = 0; g < HEADS; g++)
                s[g] += __shfl_xor_sync(0xffffffffu, s[g], off);

        // softmax over g (every lane has the full row)
        float m = s[0];
        #pragma unroll
        for (int g = 1; g < HEADS; g++) m = fmaxf(m, s[g]);
        float sum = 0.0f;
        #pragma unroll
        for (int g = 0; g < HEADS; g++) {
            s[g] = __expf(s[g] - m);
            sum += s[g];
        }
        float inv = 1.0f / sum;

        #pragma unroll
        for (int g = 0; g < HEADS; g++) {
            float p = s[g] * inv;
            o[h][0] = fmaf(p, v[g][0], o[h][0]);
            o[h][1] = fmaf(p, v[g][1], o[h][1]);
        }
    }

    float* op = out + (size_t)tok * DIM;
    if (accumulate) {
        #pragma unroll
        for (int h = 0; h < HEADS; h++) {
            op[h * HD + lane]      += o[h][0];
            op[h * HD + lane + 32] += o[h][1];
        }
    } else {
        #pragma unroll
        for (int h = 0; h < HEADS; h++) {
            op[h * HD + lane]      = o[h][0];
            op[h * HD + lane + 32] = o[h][1];
        }
    }
}

// ---------------------------------------------------------------------------
// Launch
// ---------------------------------------------------------------------------
extern "C" void kernel_launch(void* const* d_in, const int* in_sizes, int n_in,
                              void* d_out, int out_size)
{
    const float* x       = (const float*)d_in[0];
    const float* w_qkv_h = (const float*)d_in[1];
    const float* b_qkv_h = (const float*)d_in[2];
    const float* w_qkv_w = (const float*)d_in[3];
    const float* b_qkv_w = (const float*)d_in[4];
    const float* w_proj  = (const float*)d_in[5];
    const float* b_proj  = (const float*)d_in[6];
    float* out = (float*)d_out;

    float *qkv, *sum;
    cudaGetSymbolAddress((void**)&qkv, g_qkv);
    cudaGetSymbolAddress((void**)&sum, g_sum);

    dim3 gemm_qkv_grid(DIM3 / BN, T_TOK / BM);   // (18, 256)
    dim3 gemm_proj_grid(DIM / BN, T_TOK / BM);   // (6, 256)
    const int attn_grid = T_TOK / 8;             // 4096 blocks, warp per token

    // H pass
    sgemm_bias<<<gemm_qkv_grid, 256>>>(x, w_qkv_h, b_qkv_h, qkv, T_TOK, DIM3, DIM);
    head_attn<<<attn_grid, 256>>>(qkv, sum, /*acc=*/0);

    // W pass (reuses qkv scratch)
    sgemm_bias<<<gemm_qkv_grid, 256>>>(x, w_qkv_w, b_qkv_w, qkv, T_TOK, DIM3, DIM);
    head_attn<<<attn_grid, 256>>>(qkv, sum, /*acc=*/1);

    // Projection
    sgemm_bias<<<gemm_proj_grid, 256>>>(sum, w_proj, b_proj, out, T_TOK, DIM, DIM);
}

// round 4
// speedup vs baseline: 2.6481x; 2.6481x over previous
#include <cuda_runtime.h>
#include <cuda_bf16.h>
#include <cstdint>

// Problem constants
#define T_TOK   32768        // 8*64*64 tokens
#define DIM     768
#define DIM3    2304
#define HEADS   12
#define HD      64
#define NCHUNK  12           // 768 / 64
#define TILE_BYTES 16384     // 128 rows x 64 bf16 x 2B
#define STAGE_BYTES 65536    // Ah, Al, Bh, Bl tiles (16KB each)

// Scratch
__device__ float g_qkv[(size_t)T_TOK * DIM3];                       // 302 MB
__device__ float g_sum[(size_t)T_TOK * DIM];                        // 100 MB
__device__ uint8_t g_Ah[(size_t)(T_TOK/128) * NCHUNK * TILE_BYTES]; // 50.3 MB
__device__ uint8_t g_Al[(size_t)(T_TOK/128) * NCHUNK * TILE_BYTES];
__device__ uint8_t g_Bh[(size_t)(DIM3/128) * NCHUNK * TILE_BYTES];  // 3.4 MB
__device__ uint8_t g_Bl[(size_t)(DIM3/128) * NCHUNK * TILE_BYTES];

// ---------------------------------------------------------------------------
// PTX helpers (base-target only: ldmatrix / mma.sync / cp.async — NO tcgen05)
// ---------------------------------------------------------------------------
__device__ __forceinline__ uint32_t smem_u32(const void* p) {
    uint32_t a;
    asm("{ .reg .u64 t; cvta.to.shared.u64 t, %1; cvt.u32.u64 %0, t; }"
        : "=r"(a) : "l"(p));
    return a;
}

__device__ __forceinline__ void ldsm_x4(uint32_t* r, uint32_t addr) {
    asm volatile("ldmatrix.sync.aligned.m8n8.x4.shared.b16 {%0,%1,%2,%3}, [%4];"
                 : "=r"(r[0]), "=r"(r[1]), "=r"(r[2]), "=r"(r[3]) : "r"(addr));
}

__device__ __forceinline__ void mma_bf16(float* d, const uint32_t* a, const uint32_t* b) {
    asm volatile(
        "mma.sync.aligned.m16n8k16.row.col.f32.bf16.bf16.f32 "
        "{%0,%1,%2,%3}, {%4,%5,%6,%7}, {%8,%9}, {%0,%1,%2,%3};"
        : "+f"(d[0]), "+f"(d[1]), "+f"(d[2]), "+f"(d[3])
        : "r"(a[0]), "r"(a[1]), "r"(a[2]), "r"(a[3]), "r"(b[0]), "r"(b[1]));
}

__device__ __forceinline__ void cp16(uint32_t smem, const void* gmem) {
    asm volatile("cp.async.cg.shared.global [%0], [%1], 16;"
                 :: "r"(smem), "l"(gmem) : "memory");
}
#define CP_COMMIT() asm volatile("cp.async.commit_group;" ::: "memory")
#define CP_WAIT(n)  asm volatile("cp.async.wait_group %0;" :: "n"(n) : "memory")

// ---------------------------------------------------------------------------
// Convert + relayout: fp32 -> bf16 hi/lo, pre-tiled 16KB blocks, SW128-style
// swizzle: off(r, c16) = (r*128 + c16*16) ^ ((r&7)<<4).  Tile = 128 rows x 64 bf16.
// ---------------------------------------------------------------------------
union BF8 { __nv_bfloat16 b[8]; uint4 u; };

__global__ __launch_bounds__(256) void conv_split_a(
    const float* __restrict__ in, uint8_t* __restrict__ hi, uint8_t* __restrict__ lo)
{
    int idx = blockIdx.x * 256 + threadIdx.x;       // unit = 8 K-elems
    int m = idx / 96;                               // 96 units per row (768/8)
    int u = idx - m * 96;
    const float* p = in + (size_t)m * DIM + u * 8;
    float4 v0 = *(const float4*)p;
    float4 v1 = *(const float4*)(p + 4);
    float f[8] = {v0.x, v0.y, v0.z, v0.w, v1.x, v1.y, v1.z, v1.w};
    BF8 h, l;
    #pragma unroll
    for (int i = 0; i < 8; i++) {
        h.b[i] = __float2bfloat16(f[i]);
        l.b[i] = __float2bfloat16(f[i] - __bfloat162float(h.b[i]));
    }
    int mtile = m >> 7, r = m & 127, chunk = u >> 3, c16 = u & 7;
    uint32_t off = (uint32_t)(r * 128 + c16 * 16) ^ (uint32_t)((r & 7) << 4);
    size_t dst = (size_t)(mtile * NCHUNK + chunk) * TILE_BYTES + off;
    *(uint4*)(hi + dst) = h.u;
    *(uint4*)(lo + dst) = l.u;
}

// B [K=768, N] fp32 -> transposed blocks: block row = n, cols = k
__global__ __launch_bounds__(256) void conv_split_b(
    const float* __restrict__ w, uint8_t* __restrict__ hi, uint8_t* __restrict__ lo, int N)
{
    int idx = blockIdx.x * 256 + threadIdx.x;       // n * 96 + u
    int n = idx / 96;
    int u = idx - n * 96;
    int k0 = u * 8;
    BF8 h, l;
    #pragma unroll
    for (int i = 0; i < 8; i++) {
        float f = w[(size_t)(k0 + i) * N + n];
        h.b[i] = __float2bfloat16(f);
        l.b[i] = __float2bfloat16(f - __bfloat162float(h.b[i]));
    }
    int ntile = n >> 7, r = n & 127, chunk = u >> 3, c16 = u & 7;
    uint32_t off = (uint32_t)(r * 128 + c16 * 16) ^ (uint32_t)((r & 7) << 4);
    size_t dst = (size_t)(ntile * NCHUNK + chunk) * TILE_BYTES + off;
    *(uint4*)(hi + dst) = h.u;
    *(uint4*)(lo + dst) = l.u;
}

// ---------------------------------------------------------------------------
// HMMA GEMM: C[128 tile_m, 128 tile_n] = A @ B^T(pretransposed) + bias
// bf16 3-term split (AhBh + AhBl + AlBh), fp32 register accumulators.
// 256 threads = 8 warps in 4(M) x 2(N); warp tile 32 x 64.
// Double-buffered cp.async pipeline over 2 x 64KB stages.
// ---------------------------------------------------------------------------
__global__ __launch_bounds__(256) void gemm_hmma(
    const uint8_t* __restrict__ Ah, const uint8_t* __restrict__ Al,
    const uint8_t* __restrict__ Bh, const uint8_t* __restrict__ Bl,
    const float* __restrict__ bias, float* __restrict__ C, int N)
{
    extern __shared__ uint8_t smem[];
    const uint32_t sb = smem_u32(smem);

    const int tid  = threadIdx.x;
    const int lane = tid & 31;
    const int wid  = tid >> 5;
    const int wm   = wid >> 1;          // 0..3 -> M
    const int wn   = wid & 1;           // 0..1 -> N

    const int tile_n = blockIdx.x, tile_m = blockIdx.y;
    const size_t a0 = (size_t)tile_m * NCHUNK * TILE_BYTES;
    const size_t b0 = (size_t)tile_n * NCHUNK * TILE_BYTES;

    // cp.async: each thread copies 4x16B per operand per stage
    const uint32_t cp_off = (uint32_t)tid * 16;

    // ldmatrix lane-constant swizzle XOR
    const uint32_t sx = (uint32_t)((lane & 7) << 4);
    // A: row-in-16 and cg-add per lane
    const uint32_t a_r  = (uint32_t)(((lane >> 3) & 1) * 8 + (lane & 7));
    const uint32_t a_cg = (uint32_t)(lane >> 4);            // 0 or 1
    // B: row-in-16 and cg-add per lane
    const uint32_t b_r  = (uint32_t)(((lane >> 4) & 1) * 8 + (lane & 7));
    const uint32_t b_cg = (uint32_t)((lane >> 3) & 1);

    float acc[2][8][4];
    #pragma unroll
    for (int i = 0; i < 2; i++)
        #pragma unroll
        for (int j = 0; j < 8; j++)
            #pragma unroll
            for (int q = 0; q < 4; q++) acc[i][j][q] = 0.0f;

    // ---- stage load: chunk c into stage s ----
    auto load_stage = [&](int s, int c) {
        uint32_t st = sb + (uint32_t)s * STAGE_BYTES;
        size_t ko = (size_t)c * TILE_BYTES;
        #pragma unroll
        for (int q = 0; q < 4; q++) {
            uint32_t o = cp_off + (uint32_t)q * 4096;
            cp16(st +             o, Ah + a0 + ko + o);
            cp16(st + 16384 +     o, Al + a0 + ko + o);
            cp16(st + 32768 +     o, Bh + b0 + ko + o);
            cp16(st + 49152 +     o, Bl + b0 + ko + o);
        }
        CP_COMMIT();
    };

    load_stage(0, 0);

    for (int c = 0; c < NCHUNK; c++) {
        int s = c & 1;
        if (c + 1 < NCHUNK) {
            load_stage(s ^ 1, c + 1);
            CP_WAIT(1);
        } else {
            CP_WAIT(0);
        }
        __syncthreads();

        uint32_t st  = sb + (uint32_t)s * STAGE_BYTES;
        uint32_t sAh = st, sAl = st + 16384, sBh = st + 32768, sBl = st + 49152;

        #pragma unroll
        for (int ks = 0; ks < 4; ks++) {
            // A fragments: 2 m16 tiles, hi and lo
            uint32_t ah[2][4], al[2][4];
            #pragma unroll
            for (int i = 0; i < 2; i++) {
                uint32_t row = (uint32_t)(wm * 32 + i * 16) + a_r;
                uint32_t cgo = (((uint32_t)(ks * 2) + a_cg) * 16) ^ sx;
                ldsm_x4(ah[i], sAh + row * 128 + cgo);
                ldsm_x4(al[i], sAl + row * 128 + cgo);
            }
            // B: 4 groups of n16 (2 n8 tiles each)
            #pragma unroll
            for (int g = 0; g < 4; g++) {
                uint32_t bh[4], bl[4];
                uint32_t row = (uint32_t)(wn * 64 + g * 16) + b_r;
                uint32_t cgo = (((uint32_t)(ks * 2) + b_cg) * 16) ^ sx;
                ldsm_x4(bh, sBh + row * 128 + cgo);
                ldsm_x4(bl, sBl + row * 128 + cgo);
                #pragma unroll
                for (int i = 0; i < 2; i++) {
                    #pragma unroll
                    for (int jj = 0; jj < 2; jj++) {
                        float* d = acc[i][g * 2 + jj];
                        mma_bf16(d, ah[i], &bh[jj * 2]);
                        mma_bf16(d, ah[i], &bl[jj * 2]);
                        mma_bf16(d, al[i], &bh[jj * 2]);
                    }
                }
            }
        }
        __syncthreads();
    }

    // ---- epilogue: D-fragment scatter with bias ----
    const int g4 = lane >> 2, t4 = lane & 3;
    #pragma unroll
    for (int i = 0; i < 2; i++) {
        int row = tile_m * 128 + wm * 32 + i * 16 + g4;
        #pragma unroll
        for (int j = 0; j < 8; j++) {
            int col = tile_n * 128 + wn * 64 + j * 8 + t4 * 2;
            float bx = bias[col], by = bias[col + 1];
            float2 v0 = make_float2(acc[i][j][0] + bx, acc[i][j][1] + by);
            float2 v1 = make_float2(acc[i][j][2] + bx, acc[i][j][3] + by);
            *(float2*)(C + (size_t)row * N + col)       = v0;
            *(float2*)(C + (size_t)(row + 8) * N + col) = v1;
        }
    }
}

// ---------------------------------------------------------------------------
// Head-mixing attention (verified): one warp per token, 12x12 softmax.
// ---------------------------------------------------------------------------
__global__ __launch_bounds__(256) void head_attn(
    const float* __restrict__ qkv, float* __restrict__ out, int accumulate)
{
    const int lane = threadIdx.x & 31;
    const int warp = threadIdx.x >> 5;
    const int tok  = blockIdx.x * 8 + warp;
    const float* row = qkv + (size_t)tok * DIM3;
    const float scale = 0.125f;

    float k[HEADS][2], v[HEADS][2], o[HEADS][2];
    #pragma unroll
    for (int g = 0; g < HEADS; g++) {
        k[g][0] = row[DIM     + g * HD + lane];
        k[g][1] = row[DIM     + g * HD + lane + 32];
        v[g][0] = row[2 * DIM + g * HD + lane];
        v[g][1] = row[2 * DIM + g * HD + lane + 32];
        o[g][0] = 0.0f;
        o[g][1] = 0.0f;
    }

    #pragma unroll
    for (int h = 0; h < HEADS; h++) {
        float q0 = row[h * HD + lane]      * scale;
        float q1 = row[h * HD + lane + 32] * scale;

        float s[HEADS];
        #pragma unroll
        for (int g = 0; g < HEADS; g++)
            s[g] = fmaf(q0, k[g][0], q1 * k[g][1]);

        #pragma unroll
        for (int off = 16; off > 0; off >>= 1)
            #pragma unroll
            for (int g = 0; g < HEADS; g++)
                s[g] += __shfl_xor_sync(0xffffffffu, s[g], off);

        float m = s[0];
        #pragma unroll
        for (int g = 1; g < HEADS; g++) m = fmaxf(m, s[g]);
        float sum = 0.0f;
        #pragma unroll
        for (int g = 0; g < HEADS; g++) {
            s[g] = __expf(s[g] - m);
            sum += s[g];
        }
        float inv = 1.0f / sum;

        #pragma unroll
        for (int g = 0; g < HEADS; g++) {
            float p = s[g] * inv;
            o[h][0] = fmaf(p, v[g][0], o[h][0]);
            o[h][1] = fmaf(p, v[g][1], o[h][1]);
        }
    }

    float* op = out + (size_t)tok * DIM;
    if (accumulate) {
        #pragma unroll
        for (int h = 0; h < HEADS; h++) {
            op[h * HD + lane]      += o[h][0];
            op[h * HD + lane + 32] += o[h][1];
        }
    } else {
        #pragma unroll
        for (int h = 0; h < HEADS; h++) {
            op[h * HD + lane]      = o[h][0];
            op[h * HD + lane + 32] = o[h][1];
        }
    }
}

// ---------------------------------------------------------------------------
// Launch
// ---------------------------------------------------------------------------
extern "C" void kernel_launch(void* const* d_in, const int* in_sizes, int n_in,
                              void* d_out, int out_size)
{
    const float* x       = (const float*)d_in[0];
    const float* w_qkv_h = (const float*)d_in[1];
    const float* b_qkv_h = (const float*)d_in[2];
    const float* w_qkv_w = (const float*)d_in[3];
    const float* b_qkv_w = (const float*)d_in[4];
    const float* w_proj  = (const float*)d_in[5];
    const float* b_proj  = (const float*)d_in[6];
    float* out = (float*)d_out;

    float *qkv, *sum;
    uint8_t *Ah, *Al, *Bh, *Bl;
    cudaGetSymbolAddress((void**)&qkv, g_qkv);
    cudaGetSymbolAddress((void**)&sum, g_sum);
    cudaGetSymbolAddress((void**)&Ah, g_Ah);
    cudaGetSymbolAddress((void**)&Al, g_Al);
    cudaGetSymbolAddress((void**)&Bh, g_Bh);
    cudaGetSymbolAddress((void**)&Bl, g_Bl);

    const int gemm_smem = 2 * STAGE_BYTES;   // 131072 B
    cudaFuncSetAttribute(gemm_hmma,
                         cudaFuncAttributeMaxDynamicSharedMemorySize, gemm_smem);

    dim3 qkv_grid(DIM3 / 128, T_TOK / 128);   // (18, 256)
    dim3 proj_grid(DIM / 128, T_TOK / 128);   // (6, 256)
    const int attn_grid = T_TOK / 8;          // 4096

    // Convert A = x once (shared by both QKV GEMMs)
    conv_split_a<<<(T_TOK * 96) / 256, 256>>>(x, Ah, Al);

    // H pass
    conv_split_b<<<(DIM3 * 96) / 256, 256>>>(w_qkv_h, Bh, Bl, DIM3);
    gemm_hmma<<<qkv_grid, 256, gemm_smem>>>(Ah, Al, Bh, Bl, b_qkv_h, qkv, DIM3);
    head_attn<<<attn_grid, 256>>>(qkv, sum, 0);

    // W pass
    conv_split_b<<<(DIM3 * 96) / 256, 256>>>(w_qkv_w, Bh, Bl, DIM3);
    gemm_hmma<<<qkv_grid, 256, gemm_smem>>>(Ah, Al, Bh, Bl, b_qkv_w, qkv, DIM3);
    head_attn<<<attn_grid, 256>>>(qkv, sum, 1);

    // Projection
    conv_split_a<<<(T_TOK * 96) / 256, 256>>>(sum, Ah, Al);
    conv_split_b<<<(DIM * 96) / 256, 256>>>(w_proj, Bh, Bl, DIM);
    gemm_hmma<<<proj_grid, 256, gemm_smem>>>(Ah, Al, Bh, Bl, b_proj, out, DIM);
}

// round 5
// speedup vs baseline: 2.7217x; 1.0278x over previous
#include <cuda_runtime.h>
#include <cuda_bf16.h>
#include <cstdint>

// Problem constants
#define T_TOK   32768        // 8*64*64 tokens
#define DIM     768
#define DIM3    2304
#define HEADS   12
#define HD      64
#define NCHUNK  12           // 768 / 64
#define TILE_BYTES 16384     // 128 rows x 64 bf16 x 2B
#define STAGE_BYTES 65536    // Ah, Al, Bh, Bl tiles (16KB each)
#define NSTAGE  3

// Scratch
__device__ float g_qkv[(size_t)T_TOK * DIM3];                       // 302 MB
__device__ float g_sum[(size_t)T_TOK * DIM];                        // 100 MB
__device__ uint8_t g_Ah[(size_t)(T_TOK/128) * NCHUNK * TILE_BYTES]; // 50.3 MB
__device__ uint8_t g_Al[(size_t)(T_TOK/128) * NCHUNK * TILE_BYTES];
__device__ uint8_t g_Bh[(size_t)(DIM3/128) * NCHUNK * TILE_BYTES];  // 3.4 MB
__device__ uint8_t g_Bl[(size_t)(DIM3/128) * NCHUNK * TILE_BYTES];

// ---------------------------------------------------------------------------
// PTX helpers (base-target only: ldmatrix / mma.sync / cp.async)
// ---------------------------------------------------------------------------
__device__ __forceinline__ uint32_t smem_u32(const void* p) {
    uint32_t a;
    asm("{ .reg .u64 t; cvta.to.shared.u64 t, %1; cvt.u32.u64 %0, t; }"
        : "=r"(a) : "l"(p));
    return a;
}

__device__ __forceinline__ void ldsm_x4(uint32_t* r, uint32_t addr) {
    asm volatile("ldmatrix.sync.aligned.m8n8.x4.shared.b16 {%0,%1,%2,%3}, [%4];"
                 : "=r"(r[0]), "=r"(r[1]), "=r"(r[2]), "=r"(r[3]) : "r"(addr));
}

__device__ __forceinline__ void mma_bf16(float* d, const uint32_t* a, const uint32_t* b) {
    asm volatile(
        "mma.sync.aligned.m16n8k16.row.col.f32.bf16.bf16.f32 "
        "{%0,%1,%2,%3}, {%4,%5,%6,%7}, {%8,%9}, {%0,%1,%2,%3};"
        : "+f"(d[0]), "+f"(d[1]), "+f"(d[2]), "+f"(d[3])
        : "r"(a[0]), "r"(a[1]), "r"(a[2]), "r"(a[3]), "r"(b[0]), "r"(b[1]));
}

__device__ __forceinline__ void cp16(uint32_t smem, const void* gmem) {
    asm volatile("cp.async.cg.shared.global [%0], [%1], 16;"
                 :: "r"(smem), "l"(gmem) : "memory");
}
#define CP_COMMIT() asm volatile("cp.async.commit_group;" ::: "memory")
#define CP_WAIT(n)  asm volatile("cp.async.wait_group %0;" :: "n"(n) : "memory")

// ---------------------------------------------------------------------------
// Convert + relayout: fp32 -> bf16 hi/lo, pre-tiled 16KB blocks, SW128-style
// swizzle: off(r, c16) = (r*128 + c16*16) ^ ((r&7)<<4).  Tile = 128 rows x 64 bf16.
// ---------------------------------------------------------------------------
union BF8 { __nv_bfloat16 b[8]; uint4 u; };

__global__ __launch_bounds__(256) void conv_split_a(
    const float* __restrict__ in, uint8_t* __restrict__ hi, uint8_t* __restrict__ lo)
{
    int idx = blockIdx.x * 256 + threadIdx.x;       // unit = 8 K-elems
    int m = idx / 96;                               // 96 units per row (768/8)
    int u = idx - m * 96;
    const float* p = in + (size_t)m * DIM + u * 8;
    float4 v0 = *(const float4*)p;
    float4 v1 = *(const float4*)(p + 4);
    float f[8] = {v0.x, v0.y, v0.z, v0.w, v1.x, v1.y, v1.z, v1.w};
    BF8 h, l;
    #pragma unroll
    for (int i = 0; i < 8; i++) {
        h.b[i] = __float2bfloat16(f[i]);
        l.b[i] = __float2bfloat16(f[i] - __bfloat162float(h.b[i]));
    }
    int mtile = m >> 7, r = m & 127, chunk = u >> 3, c16 = u & 7;
    uint32_t off = (uint32_t)(r * 128 + c16 * 16) ^ (uint32_t)((r & 7) << 4);
    size_t dst = (size_t)(mtile * NCHUNK + chunk) * TILE_BYTES + off;
    *(uint4*)(hi + dst) = h.u;
    *(uint4*)(lo + dst) = l.u;
}

// B [K=768, N] fp32 -> transposed blocks: block row = n, cols = k
__global__ __launch_bounds__(256) void conv_split_b(
    const float* __restrict__ w, uint8_t* __restrict__ hi, uint8_t* __restrict__ lo, int N)
{
    int idx = blockIdx.x * 256 + threadIdx.x;       // n * 96 + u
    int n = idx / 96;
    int u = idx - n * 96;
    int k0 = u * 8;
    BF8 h, l;
    #pragma unroll
    for (int i = 0; i < 8; i++) {
        float f = w[(size_t)(k0 + i) * N + n];
        h.b[i] = __float2bfloat16(f);
        l.b[i] = __float2bfloat16(f - __bfloat162float(h.b[i]));
    }
    int ntile = n >> 7, r = n & 127, chunk = u >> 3, c16 = u & 7;
    uint32_t off = (uint32_t)(r * 128 + c16 * 16) ^ (uint32_t)((r & 7) << 4);
    size_t dst = (size_t)(ntile * NCHUNK + chunk) * TILE_BYTES + off;
    *(uint4*)(hi + dst) = h.u;
    *(uint4*)(lo + dst) = l.u;
}

// ---------------------------------------------------------------------------
// HMMA GEMM: C[128 tile_m, 128 tile_n] = A @ B^T(pretransposed) + bias
// bf16 3-term split (AhBh + AhBl + AlBh), fp32 register accumulators.
// 128 threads = 4 warps in 2(M) x 2(N); warp tile 64 x 64 (less smem re-read).
// 3-stage cp.async pipeline over 3 x 64KB stages (192KB smem).
// ---------------------------------------------------------------------------
__global__ __launch_bounds__(128, 1) void gemm_hmma(
    const uint8_t* __restrict__ Ah, const uint8_t* __restrict__ Al,
    const uint8_t* __restrict__ Bh, const uint8_t* __restrict__ Bl,
    const float* __restrict__ bias, float* __restrict__ C, int N)
{
    extern __shared__ uint8_t smem[];
    const uint32_t sb = smem_u32(smem);

    const int tid  = threadIdx.x;
    const int lane = tid & 31;
    const int wid  = tid >> 5;
    const int wm   = wid >> 1;          // 0..1 -> M (64 rows each)
    const int wn   = wid & 1;           // 0..1 -> N (64 cols each)

    const int tile_n = blockIdx.x, tile_m = blockIdx.y;
    const size_t a0 = (size_t)tile_m * NCHUNK * TILE_BYTES;
    const size_t b0 = (size_t)tile_n * NCHUNK * TILE_BYTES;

    // cp.async: 128 threads x 8 iters x 16B = 16KB per operand tile
    const uint32_t cp_off = (uint32_t)tid * 16;

    // ldmatrix lane-constant swizzle XOR (verified mapping from round 4)
    const uint32_t sx   = (uint32_t)((lane & 7) << 4);
    const uint32_t a_r  = (uint32_t)(((lane >> 3) & 1) * 8 + (lane & 7));
    const uint32_t a_cg = (uint32_t)(lane >> 4);            // 0 or 1
    const uint32_t b_r  = (uint32_t)(((lane >> 4) & 1) * 8 + (lane & 7));
    const uint32_t b_cg = (uint32_t)((lane >> 3) & 1);

    // 64x64 warp tile: 4 m16 x 8 n8 fragments
    float acc[4][8][4];
    #pragma unroll
    for (int i = 0; i < 4; i++)
        #pragma unroll
        for (int j = 0; j < 8; j++)
            #pragma unroll
            for (int q = 0; q < 4; q++) acc[i][j][q] = 0.0f;

    auto load_stage = [&](int s, int c) {
        uint32_t st = sb + (uint32_t)s * STAGE_BYTES;
        size_t ko = (size_t)c * TILE_BYTES;
        #pragma unroll
        for (int q = 0; q < 8; q++) {
            uint32_t o = cp_off + (uint32_t)q * 2048;
            cp16(st +         o, Ah + a0 + ko + o);
            cp16(st + 16384 + o, Al + a0 + ko + o);
            cp16(st + 32768 + o, Bh + b0 + ko + o);
            cp16(st + 49152 + o, Bl + b0 + ko + o);
        }
        CP_COMMIT();
    };

    // Prologue: fill all 3 stages
    #pragma unroll
    for (int s = 0; s < NSTAGE; s++) load_stage(s, s);

    for (int c = 0; c < NCHUNK; c++) {
        // wait for chunk c's group: #newer groups in flight = min(NCHUNK-1-c, 2)
        if (c < NCHUNK - 2)       CP_WAIT(2);
        else if (c == NCHUNK - 2) CP_WAIT(1);
        else                      CP_WAIT(0);
        __syncthreads();

        uint32_t st  = sb + (uint32_t)(c % NSTAGE) * STAGE_BYTES;
        uint32_t sAh = st, sAl = st + 16384, sBh = st + 32768, sBl = st + 49152;

        #pragma unroll
        for (int ks = 0; ks < 4; ks++) {
            // A fragments: 4 m16 tiles, hi and lo
            uint32_t ah[4][4], al[4][4];
            #pragma unroll
            for (int i = 0; i < 4; i++) {
                uint32_t row = (uint32_t)(wm * 64 + i * 16) + a_r;
                uint32_t cgo = (((uint32_t)(ks * 2) + a_cg) * 16) ^ sx;
                ldsm_x4(ah[i], sAh + row * 128 + cgo);
                ldsm_x4(al[i], sAl + row * 128 + cgo);
            }
            // B: 4 groups of n16 (2 n8 tiles each)
            #pragma unroll
            for (int g = 0; g < 4; g++) {
                uint32_t bh[4], bl[4];
                uint32_t row = (uint32_t)(wn * 64 + g * 16) + b_r;
                uint32_t cgo = (((uint32_t)(ks * 2) + b_cg) * 16) ^ sx;
                ldsm_x4(bh, sBh + row * 128 + cgo);
                ldsm_x4(bl, sBl + row * 128 + cgo);
                #pragma unroll
                for (int i = 0; i < 4; i++) {
                    #pragma unroll
                    for (int jj = 0; jj < 2; jj++) {
                        float* d = acc[i][g * 2 + jj];
                        mma_bf16(d, ah[i], &bh[jj * 2]);
                        mma_bf16(d, ah[i], &bl[jj * 2]);
                        mma_bf16(d, al[i], &bh[jj * 2]);
                    }
                }
            }
        }
        __syncthreads();

        if (c + NSTAGE < NCHUNK) load_stage(c % NSTAGE, c + NSTAGE);
    }

    // ---- epilogue: D-fragment scatter with bias ----
    const int g4 = lane >> 2, t4 = lane & 3;
    #pragma unroll
    for (int i = 0; i < 4; i++) {
        int row = tile_m * 128 + wm * 64 + i * 16 + g4;
        #pragma unroll
        for (int j = 0; j < 8; j++) {
            int col = tile_n * 128 + wn * 64 + j * 8 + t4 * 2;
            float bx = bias[col], by = bias[col + 1];
            float2 v0 = make_float2(acc[i][j][0] + bx, acc[i][j][1] + by);
            float2 v1 = make_float2(acc[i][j][2] + bx, acc[i][j][3] + by);
            *(float2*)(C + (size_t)row * N + col)       = v0;
            *(float2*)(C + (size_t)(row + 8) * N + col) = v1;
        }
    }
}

// ---------------------------------------------------------------------------
// Head-mixing attention (verified): one warp per token, 12x12 softmax.
// ---------------------------------------------------------------------------
__global__ __launch_bounds__(256) void head_attn(
    const float* __restrict__ qkv, float* __restrict__ out, int accumulate)
{
    const int lane = threadIdx.x & 31;
    const int warp = threadIdx.x >> 5;
    const int tok  = blockIdx.x * 8 + warp;
    const float* row = qkv + (size_t)tok * DIM3;
    const float scale = 0.125f;

    float k[HEADS][2], v[HEADS][2], o[HEADS][2];
    #pragma unroll
    for (int g = 0; g < HEADS; g++) {
        k[g][0] = row[DIM     + g * HD + lane];
        k[g][1] = row[DIM     + g * HD + lane + 32];
        v[g][0] = row[2 * DIM + g * HD + lane];
        v[g][1] = row[2 * DIM + g * HD + lane + 32];
        o[g][0] = 0.0f;
        o[g][1] = 0.0f;
    }

    #pragma unroll
    for (int h = 0; h < HEADS; h++) {
        float q0 = row[h * HD + lane]      * scale;
        float q1 = row[h * HD + lane + 32] * scale;

        float s[HEADS];
        #pragma unroll
        for (int g = 0; g < HEADS; g++)
            s[g] = fmaf(q0, k[g][0], q1 * k[g][1]);

        #pragma unroll
        for (int off = 16; off > 0; off >>= 1)
            #pragma unroll
            for (int g = 0; g < HEADS; g++)
                s[g] += __shfl_xor_sync(0xffffffffu, s[g], off);

        float m = s[0];
        #pragma unroll
        for (int g = 1; g < HEADS; g++) m = fmaxf(m, s[g]);
        float sum = 0.0f;
        #pragma unroll
        for (int g = 0; g < HEADS; g++) {
            s[g] = __expf(s[g] - m);
            sum += s[g];
        }
        float inv = 1.0f / sum;

        #pragma unroll
        for (int g = 0; g < HEADS; g++) {
            float p = s[g] * inv;
            o[h][0] = fmaf(p, v[g][0], o[h][0]);
            o[h][1] = fmaf(p, v[g][1], o[h][1]);
        }
    }

    float* op = out + (size_t)tok * DIM;
    if (accumulate) {
        #pragma unroll
        for (int h = 0; h < HEADS; h++) {
            op[h * HD + lane]      += o[h][0];
            op[h * HD + lane + 32] += o[h][1];
        }
    } else {
        #pragma unroll
        for (int h = 0; h < HEADS; h++) {
            op[h * HD + lane]      = o[h][0];
            op[h * HD + lane + 32] = o[h][1];
        }
    }
}

// ---------------------------------------------------------------------------
// Launch
// ---------------------------------------------------------------------------
extern "C" void kernel_launch(void* const* d_in, const int* in_sizes, int n_in,
                              void* d_out, int out_size)
{
    const float* x       = (const float*)d_in[0];
    const float* w_qkv_h = (const float*)d_in[1];
    const float* b_qkv_h = (const float*)d_in[2];
    const float* w_qkv_w = (const float*)d_in[3];
    const float* b_qkv_w = (const float*)d_in[4];
    const float* w_proj  = (const float*)d_in[5];
    const float* b_proj  = (const float*)d_in[6];
    float* out = (float*)d_out;

    float *qkv, *sum;
    uint8_t *Ah, *Al, *Bh, *Bl;
    cudaGetSymbolAddress((void**)&qkv, g_qkv);
    cudaGetSymbolAddress((void**)&sum, g_sum);
    cudaGetSymbolAddress((void**)&Ah, g_Ah);
    cudaGetSymbolAddress((void**)&Al, g_Al);
    cudaGetSymbolAddress((void**)&Bh, g_Bh);
    cudaGetSymbolAddress((void**)&Bl, g_Bl);

    const int gemm_smem = NSTAGE * STAGE_BYTES;   // 196608 B
    cudaFuncSetAttribute(gemm_hmma,
                         cudaFuncAttributeMaxDynamicSharedMemorySize, gemm_smem);

    dim3 qkv_grid(DIM3 / 128, T_TOK / 128);   // (18, 256)
    dim3 proj_grid(DIM / 128, T_TOK / 128);   // (6, 256)
    const int attn_grid = T_TOK / 8;          // 4096

    // Convert A = x once (shared by both QKV GEMMs)
    conv_split_a<<<(T_TOK * 96) / 256, 256>>>(x, Ah, Al);

    // H pass
    conv_split_b<<<(DIM3 * 96) / 256, 256>>>(w_qkv_h, Bh, Bl, DIM3);
    gemm_hmma<<<qkv_grid, 128, gemm_smem>>>(Ah, Al, Bh, Bl, b_qkv_h, qkv, DIM3);
    head_attn<<<attn_grid, 256>>>(qkv, sum, 0);

    // W pass
    conv_split_b<<<(DIM3 * 96) / 256, 256>>>(w_qkv_w, Bh, Bl, DIM3);
    gemm_hmma<<<qkv_grid, 128, gemm_smem>>>(Ah, Al, Bh, Bl, b_qkv_w, qkv, DIM3);
    head_attn<<<attn_grid, 256>>>(qkv, sum, 1);

    // Projection
    conv_split_a<<<(T_TOK * 96) / 256, 256>>>(sum, Ah, Al);
    conv_split_b<<<(DIM * 96) / 256, 256>>>(w_proj, Bh, Bl, DIM);
    gemm_hmma<<<proj_grid, 128, gemm_smem>>>(Ah, Al, Bh, Bl, b_proj, out, DIM);
}

// round 6
// speedup vs baseline: 5.5477x; 2.0383x over previous
#include <cuda_runtime.h>
#include <cuda_fp16.h>
#include <cstdint>

// Problem constants
#define T_TOK   32768        // 8*64*64 tokens
#define DIM     768
#define DIM3    2304
#define HEADS   12
#define HD      64
#define NCHUNK  12           // 768 / 64
#define TILE_BYTES 16384     // 128 rows x 64 fp16 x 2B
#define STAGE_BYTES 32768    // A tile + B tile
#define NSTAGE  3

// Scratch
__device__ float g_qkv[(size_t)T_TOK * DIM3];                       // 302 MB
__device__ float g_sum[(size_t)T_TOK * DIM];                        // 100 MB
__device__ uint8_t g_A[(size_t)(T_TOK/128) * NCHUNK * TILE_BYTES];  // 50.3 MB
__device__ uint8_t g_B[(size_t)(DIM3/128) * NCHUNK * TILE_BYTES];   // 3.4 MB

// ---------------------------------------------------------------------------
// PTX helpers (base-target only: ldmatrix / mma.sync / cp.async)
// ---------------------------------------------------------------------------
__device__ __forceinline__ uint32_t smem_u32(const void* p) {
    uint32_t a;
    asm("{ .reg .u64 t; cvta.to.shared.u64 t, %1; cvt.u32.u64 %0, t; }"
        : "=r"(a) : "l"(p));
    return a;
}

__device__ __forceinline__ void ldsm_x4(uint32_t* r, uint32_t addr) {
    asm volatile("ldmatrix.sync.aligned.m8n8.x4.shared.b16 {%0,%1,%2,%3}, [%4];"
                 : "=r"(r[0]), "=r"(r[1]), "=r"(r[2]), "=r"(r[3]) : "r"(addr));
}

__device__ __forceinline__ void mma_f16(float* d, const uint32_t* a, const uint32_t* b) {
    asm volatile(
        "mma.sync.aligned.m16n8k16.row.col.f32.f16.f16.f32 "
        "{%0,%1,%2,%3}, {%4,%5,%6,%7}, {%8,%9}, {%0,%1,%2,%3};"
        : "+f"(d[0]), "+f"(d[1]), "+f"(d[2]), "+f"(d[3])
        : "r"(a[0]), "r"(a[1]), "r"(a[2]), "r"(a[3]), "r"(b[0]), "r"(b[1]));
}

__device__ __forceinline__ void cp16(uint32_t smem, const void* gmem) {
    asm volatile("cp.async.cg.shared.global [%0], [%1], 16;"
                 :: "r"(smem), "l"(gmem) : "memory");
}
#define CP_COMMIT() asm volatile("cp.async.commit_group;" ::: "memory")
#define CP_WAIT(n)  asm volatile("cp.async.wait_group %0;" :: "n"(n) : "memory")

// ---------------------------------------------------------------------------
// Convert + relayout: fp32 -> fp16, pre-tiled 16KB blocks, SW128-style
// swizzle: off(r, c16) = (r*128 + c16*16) ^ ((r&7)<<4).  Tile = 128 rows x 64 fp16.
// ---------------------------------------------------------------------------
union HF8 { __half h[8]; uint4 u; };

__global__ __launch_bounds__(256) void conv_a(
    const float* __restrict__ in, uint8_t* __restrict__ dst)
{
    int idx = blockIdx.x * 256 + threadIdx.x;       // unit = 8 K-elems
    int m = idx / 96;                               // 96 units per row (768/8)
    int u = idx - m * 96;
    const float* p = in + (size_t)m * DIM + u * 8;
    float4 v0 = *(const float4*)p;
    float4 v1 = *(const float4*)(p + 4);
    float f[8] = {v0.x, v0.y, v0.z, v0.w, v1.x, v1.y, v1.z, v1.w};
    HF8 h;
    #pragma unroll
    for (int i = 0; i < 8; i++) h.h[i] = __float2half_rn(f[i]);
    int mtile = m >> 7, r = m & 127, chunk = u >> 3, c16 = u & 7;
    uint32_t off = (uint32_t)(r * 128 + c16 * 16) ^ (uint32_t)((r & 7) << 4);
    *(uint4*)(dst + (size_t)(mtile * NCHUNK + chunk) * TILE_BYTES + off) = h.u;
}

// B [K=768, N] fp32 -> transposed tiles: tile row = n, cols = k
__global__ __launch_bounds__(256) void conv_b(
    const float* __restrict__ w, uint8_t* __restrict__ dst, int N)
{
    int idx = blockIdx.x * 256 + threadIdx.x;       // n * 96 + u
    int n = idx / 96;
    int u = idx - n * 96;
    int k0 = u * 8;
    HF8 h;
    #pragma unroll
    for (int i = 0; i < 8; i++)
        h.h[i] = __float2half_rn(w[(size_t)(k0 + i) * N + n]);
    int ntile = n >> 7, r = n & 127, chunk = u >> 3, c16 = u & 7;
    uint32_t off = (uint32_t)(r * 128 + c16 * 16) ^ (uint32_t)((r & 7) << 4);
    *(uint4*)(dst + (size_t)(ntile * NCHUNK + chunk) * TILE_BYTES + off) = h.u;
}

// ---------------------------------------------------------------------------
// HMMA GEMM: C[128 tile_m, 128 tile_n] = A @ B^T(pretransposed) + bias
// fp16 single-term, fp32 register accumulators.
// 256 threads = 8 warps in 4(M) x 2(N); warp tile 32 x 64.
// 3-stage cp.async pipeline, 96KB smem -> 2 CTAs/SM.
// ---------------------------------------------------------------------------
__global__ __launch_bounds__(256, 2) void gemm_hmma(
    const uint8_t* __restrict__ A, const uint8_t* __restrict__ B,
    const float* __restrict__ bias, float* __restrict__ C, int N)
{
    extern __shared__ uint8_t smem[];
    const uint32_t sb = smem_u32(smem);

    const int tid  = threadIdx.x;
    const int lane = tid & 31;
    const int wid  = tid >> 5;
    const int wm   = wid >> 1;          // 0..3 -> M (32 rows each)
    const int wn   = wid & 1;           // 0..1 -> N (64 cols each)

    const int tile_n = blockIdx.x, tile_m = blockIdx.y;
    const size_t a0 = (size_t)tile_m * NCHUNK * TILE_BYTES;
    const size_t b0 = (size_t)tile_n * NCHUNK * TILE_BYTES;

    // cp.async: 256 threads x 4 iters x 16B = 16KB per operand tile
    const uint32_t cp_off = (uint32_t)tid * 16;

    // ldmatrix lane maps (verified rounds 4-5)
    const uint32_t sx   = (uint32_t)((lane & 7) << 4);
    const uint32_t a_r  = (uint32_t)(((lane >> 3) & 1) * 8 + (lane & 7));
    const uint32_t a_cg = (uint32_t)(lane >> 4);            // 0 or 1
    const uint32_t b_r  = (uint32_t)(((lane >> 4) & 1) * 8 + (lane & 7));
    const uint32_t b_cg = (uint32_t)((lane >> 3) & 1);

    // 32x64 warp tile: 2 m16 x 8 n8 fragments
    float acc[2][8][4];
    #pragma unroll
    for (int i = 0; i < 2; i++)
        #pragma unroll
        for (int j = 0; j < 8; j++)
            #pragma unroll
            for (int q = 0; q < 4; q++) acc[i][j][q] = 0.0f;

    auto load_stage = [&](int s, int c) {
        uint32_t st = sb + (uint32_t)s * STAGE_BYTES;
        size_t ko = (size_t)c * TILE_BYTES;
        #pragma unroll
        for (int q = 0; q < 4; q++) {
            uint32_t o = cp_off + (uint32_t)q * 4096;
            cp16(st +         o, A + a0 + ko + o);
            cp16(st + 16384 + o, B + b0 + ko + o);
        }
        CP_COMMIT();
    };

    // Prologue: fill all 3 stages
    #pragma unroll
    for (int s = 0; s < NSTAGE; s++) load_stage(s, s);

    for (int c = 0; c < NCHUNK; c++) {
        if (c < NCHUNK - 2)       CP_WAIT(2);
        else if (c == NCHUNK - 2) CP_WAIT(1);
        else                      CP_WAIT(0);
        __syncthreads();

        uint32_t st = sb + (uint32_t)(c % NSTAGE) * STAGE_BYTES;
        uint32_t sA = st, sB = st + 16384;

        #pragma unroll
        for (int ks = 0; ks < 4; ks++) {
            uint32_t a[2][4];
            #pragma unroll
            for (int i = 0; i < 2; i++) {
                uint32_t row = (uint32_t)(wm * 32 + i * 16) + a_r;
                uint32_t cgo = (((uint32_t)(ks * 2) + a_cg) * 16) ^ sx;
                ldsm_x4(a[i], sA + row * 128 + cgo);
            }
            #pragma unroll
            for (int g = 0; g < 4; g++) {
                uint32_t b[4];
                uint32_t row = (uint32_t)(wn * 64 + g * 16) + b_r;
                uint32_t cgo = (((uint32_t)(ks * 2) + b_cg) * 16) ^ sx;
                ldsm_x4(b, sB + row * 128 + cgo);
                #pragma unroll
                for (int i = 0; i < 2; i++) {
                    mma_f16(acc[i][g * 2 + 0], a[i], &b[0]);
                    mma_f16(acc[i][g * 2 + 1], a[i], &b[2]);
                }
            }
        }
        __syncthreads();

        if (c + NSTAGE < NCHUNK) load_stage(c % NSTAGE, c + NSTAGE);
    }

    // ---- epilogue: D-fragment scatter with bias ----
    const int g4 = lane >> 2, t4 = lane & 3;
    #pragma unroll
    for (int i = 0; i < 2; i++) {
        int row = tile_m * 128 + wm * 32 + i * 16 + g4;
        #pragma unroll
        for (int j = 0; j < 8; j++) {
            int col = tile_n * 128 + wn * 64 + j * 8 + t4 * 2;
            float bx = bias[col], by = bias[col + 1];
            float2 v0 = make_float2(acc[i][j][0] + bx, acc[i][j][1] + by);
            float2 v1 = make_float2(acc[i][j][2] + bx, acc[i][j][3] + by);
            *(float2*)(C + (size_t)row * N + col)       = v0;
            *(float2*)(C + (size_t)(row + 8) * N + col) = v1;
        }
    }
}

// ---------------------------------------------------------------------------
// Head-mixing attention: one warp per token, 12x12 softmax across heads.
// float2 layout: lane owns d-pair (2*lane, 2*lane+1).
// ---------------------------------------------------------------------------
__global__ __launch_bounds__(256) void head_attn(
    const float* __restrict__ qkv, float* __restrict__ out, int accumulate)
{
    const int lane = threadIdx.x & 31;
    const int warp = threadIdx.x >> 5;
    const int tok  = blockIdx.x * 8 + warp;
    const float* row = qkv + (size_t)tok * DIM3;
    const float scale = 0.125f;
    const int d2 = lane * 2;

    float2 k[HEADS], v[HEADS], o[HEADS];
    #pragma unroll
    for (int g = 0; g < HEADS; g++) {
        k[g] = *(const float2*)(row + DIM     + g * HD + d2);
        v[g] = *(const float2*)(row + 2 * DIM + g * HD + d2);
        o[g] = make_float2(0.0f, 0.0f);
    }

    #pragma unroll
    for (int h = 0; h < HEADS; h++) {
        float2 q = *(const float2*)(row + h * HD + d2);
        q.x *= scale; q.y *= scale;

        float s[HEADS];
        #pragma unroll
        for (int g = 0; g < HEADS; g++)
            s[g] = fmaf(q.x, k[g].x, q.y * k[g].y);

        #pragma unroll
        for (int off = 16; off > 0; off >>= 1)
            #pragma unroll
            for (int g = 0; g < HEADS; g++)
                s[g] += __shfl_xor_sync(0xffffffffu, s[g], off);

        float m = s[0];
        #pragma unroll
        for (int g = 1; g < HEADS; g++) m = fmaxf(m, s[g]);
        float sum = 0.0f;
        #pragma unroll
        for (int g = 0; g < HEADS; g++) {
            s[g] = __expf(s[g] - m);
            sum += s[g];
        }
        float inv = 1.0f / sum;

        #pragma unroll
        for (int g = 0; g < HEADS; g++) {
            float p = s[g] * inv;
            o[h].x = fmaf(p, v[g].x, o[h].x);
            o[h].y = fmaf(p, v[g].y, o[h].y);
        }
    }

    float* op = out + (size_t)tok * DIM;
    if (accumulate) {
        #pragma unroll
        for (int h = 0; h < HEADS; h++) {
            float2 cur = *(float2*)(op + h * HD + d2);
            cur.x += o[h].x; cur.y += o[h].y;
            *(float2*)(op + h * HD + d2) = cur;
        }
    } else {
        #pragma unroll
        for (int h = 0; h < HEADS; h++)
            *(float2*)(op + h * HD + d2) = o[h];
    }
}

// ---------------------------------------------------------------------------
// Launch
// ---------------------------------------------------------------------------
extern "C" void kernel_launch(void* const* d_in, const int* in_sizes, int n_in,
                              void* d_out, int out_size)
{
    const float* x       = (const float*)d_in[0];
    const float* w_qkv_h = (const float*)d_in[1];
    const float* b_qkv_h = (const float*)d_in[2];
    const float* w_qkv_w = (const float*)d_in[3];
    const float* b_qkv_w = (const float*)d_in[4];
    const float* w_proj  = (const float*)d_in[5];
    const float* b_proj  = (const float*)d_in[6];
    float* out = (float*)d_out;

    float *qkv, *sum;
    uint8_t *A, *B;
    cudaGetSymbolAddress((void**)&qkv, g_qkv);
    cudaGetSymbolAddress((void**)&sum, g_sum);
    cudaGetSymbolAddress((void**)&A, g_A);
    cudaGetSymbolAddress((void**)&B, g_B);

    const int gemm_smem = NSTAGE * STAGE_BYTES;   // 98304 B
    cudaFuncSetAttribute(gemm_hmma,
                         cudaFuncAttributeMaxDynamicSharedMemorySize, gemm_smem);

    dim3 qkv_grid(DIM3 / 128, T_TOK / 128);   // (18, 256)
    dim3 proj_grid(DIM / 128, T_TOK / 128);   // (6, 256)
    const int attn_grid = T_TOK / 8;          // 4096

    // Convert A = x once (shared by both QKV GEMMs)
    conv_a<<<(T_TOK * 96) / 256, 256>>>(x, A);

    // H pass
    conv_b<<<(DIM3 * 96) / 256, 256>>>(w_qkv_h, B, DIM3);
    gemm_hmma<<<qkv_grid, 256, gemm_smem>>>(A, B, b_qkv_h, qkv, DIM3);
    head_attn<<<attn_grid, 256>>>(qkv, sum, 0);

    // W pass
    conv_b<<<(DIM3 * 96) / 256, 256>>>(w_qkv_w, B, DIM3);
    gemm_hmma<<<qkv_grid, 256, gemm_smem>>>(A, B, b_qkv_w, qkv, DIM3);
    head_attn<<<attn_grid, 256>>>(qkv, sum, 1);

    // Projection
    conv_a<<<(T_TOK * 96) / 256, 256>>>(sum, A);
    conv_b<<<(DIM * 96) / 256, 256>>>(w_proj, B, DIM);
    gemm_hmma<<<proj_grid, 256, gemm_smem>>>(A, B, b_proj, out, DIM);
}

// round 7
// speedup vs baseline: 5.9998x; 1.0815x over previous
#include <cuda_runtime.h>
#include <cuda_fp16.h>
#include <cstdint>

// Problem constants
#define T_TOK   32768        // 8*64*64 tokens
#define DIM     768
#define DIM3    2304
#define HEADS   12
#define HD      64
#define NCHUNK  12           // 768 / 64 (K chunks per tile row)
#define TILE_BYTES 16384     // 128 rows x 64 fp16 x 2B
#define STAGE_BYTES 32768    // A tile + B tile
#define NSTAGE  3

// Scratch (all fp16 tiled/swizzled except none)
__device__ uint8_t g_A  [(size_t)(T_TOK/128) * NCHUNK * TILE_BYTES];  // x as fp16 tiles, 50MB
__device__ uint8_t g_Bh [(size_t)(DIM3/128) * NCHUNK * TILE_BYTES];   // 3.4MB
__device__ uint8_t g_Bw [(size_t)(DIM3/128) * NCHUNK * TILE_BYTES];
__device__ uint8_t g_Bp [(size_t)(DIM/128) * NCHUNK * TILE_BYTES];    // 1.2MB
__device__ uint8_t g_qkvh[(size_t)(T_TOK/128) * 36 * TILE_BYTES];     // 151MB
__device__ uint8_t g_qkvw[(size_t)(T_TOK/128) * 36 * TILE_BYTES];     // 151MB
__device__ uint8_t g_Ao [(size_t)(T_TOK/128) * NCHUNK * TILE_BYTES];  // attn out tiles, 50MB

// ---------------------------------------------------------------------------
// PTX helpers (base-target only: ldmatrix / mma.sync / cp.async)
// ---------------------------------------------------------------------------
__device__ __forceinline__ uint32_t smem_u32(const void* p) {
    uint32_t a;
    asm("{ .reg .u64 t; cvta.to.shared.u64 t, %1; cvt.u32.u64 %0, t; }"
        : "=r"(a) : "l"(p));
    return a;
}

__device__ __forceinline__ void ldsm_x4(uint32_t* r, uint32_t addr) {
    asm volatile("ldmatrix.sync.aligned.m8n8.x4.shared.b16 {%0,%1,%2,%3}, [%4];"
                 : "=r"(r[0]), "=r"(r[1]), "=r"(r[2]), "=r"(r[3]) : "r"(addr));
}

__device__ __forceinline__ void mma_f16(float* d, const uint32_t* a, const uint32_t* b) {
    asm volatile(
        "mma.sync.aligned.m16n8k16.row.col.f32.f16.f16.f32 "
        "{%0,%1,%2,%3}, {%4,%5,%6,%7}, {%8,%9}, {%0,%1,%2,%3};"
        : "+f"(d[0]), "+f"(d[1]), "+f"(d[2]), "+f"(d[3])
        : "r"(a[0]), "r"(a[1]), "r"(a[2]), "r"(a[3]), "r"(b[0]), "r"(b[1]));
}

__device__ __forceinline__ void cp16(uint32_t smem, const void* gmem) {
    asm volatile("cp.async.cg.shared.global [%0], [%1], 16;"
                 :: "r"(smem), "l"(gmem) : "memory");
}
#define CP_COMMIT() asm volatile("cp.async.commit_group;" ::: "memory")
#define CP_WAIT(n)  asm volatile("cp.async.wait_group %0;" :: "n"(n) : "memory")

// ---------------------------------------------------------------------------
// Convert + relayout: fp32 -> fp16, pre-tiled 16KB blocks, SW128-style
// swizzle: off(r, c16) = (r*128 + c16*16) ^ ((r&7)<<4).  Tile = 128 rows x 64 fp16.
// ---------------------------------------------------------------------------
union HF8 { __half h[8]; uint4 u; };

__global__ __launch_bounds__(256) void conv_a(
    const float* __restrict__ in, uint8_t* __restrict__ dst)
{
    int idx = blockIdx.x * 256 + threadIdx.x;       // unit = 8 K-elems
    int m = idx / 96;                               // 96 units per row (768/8)
    int u = idx - m * 96;
    const float* p = in + (size_t)m * DIM + u * 8;
    float4 v0 = *(const float4*)p;
    float4 v1 = *(const float4*)(p + 4);
    float f[8] = {v0.x, v0.y, v0.z, v0.w, v1.x, v1.y, v1.z, v1.w};
    HF8 h;
    #pragma unroll
    for (int i = 0; i < 8; i++) h.h[i] = __float2half_rn(f[i]);
    int mtile = m >> 7, r = m & 127, chunk = u >> 3, c16 = u & 7;
    uint32_t off = (uint32_t)(r * 128 + c16 * 16) ^ (uint32_t)((r & 7) << 4);
    *(uint4*)(dst + (size_t)(mtile * NCHUNK + chunk) * TILE_BYTES + off) = h.u;
}

// B [K=768, N] fp32 -> transposed tiles: tile row = n, cols = k
__global__ __launch_bounds__(256) void conv_b(
    const float* __restrict__ w, uint8_t* __restrict__ dst, int N)
{
    int idx = blockIdx.x * 256 + threadIdx.x;       // n * 96 + u
    int n = idx / 96;
    int u = idx - n * 96;
    int k0 = u * 8;
    HF8 h;
    #pragma unroll
    for (int i = 0; i < 8; i++)
        h.h[i] = __float2half_rn(w[(size_t)(k0 + i) * N + n]);
    int ntile = n >> 7, r = n & 127, chunk = u >> 3, c16 = u & 7;
    uint32_t off = (uint32_t)(r * 128 + c16 * 16) ^ (uint32_t)((r & 7) << 4);
    *(uint4*)(dst + (size_t)(ntile * NCHUNK + chunk) * TILE_BYTES + off) = h.u;
}

// ---------------------------------------------------------------------------
// HMMA GEMM core: C[128 tile_m, 128 tile_n] = A @ B^T(pretransposed) + bias
// fp16 inputs, fp32 register accumulators.
// 256 threads = 8 warps in 4(M) x 2(N); warp tile 32 x 64.
// 3-stage cp.async pipeline, 96KB smem -> 2 CTAs/SM.
// OUT_F16=0: fp32 row-major (stride N). OUT_F16=1: fp16 tiled+swizzled,
//            chunk index = tile_n*2 + wn, N/64 chunks per m-tile.
// ---------------------------------------------------------------------------
template <int OUT_F16>
__global__ __launch_bounds__(256, 2) void gemm_hmma(
    const uint8_t* __restrict__ A, const uint8_t* __restrict__ B,
    const float* __restrict__ bias, void* __restrict__ Cout, int N)
{
    extern __shared__ uint8_t smem[];
    const uint32_t sb = smem_u32(smem);

    const int tid  = threadIdx.x;
    const int lane = tid & 31;
    const int wid  = tid >> 5;
    const int wm   = wid >> 1;          // 0..3 -> M (32 rows each)
    const int wn   = wid & 1;           // 0..1 -> N (64 cols each)

    const int tile_n = blockIdx.x, tile_m = blockIdx.y;
    const size_t a0 = (size_t)tile_m * NCHUNK * TILE_BYTES;
    const size_t b0 = (size_t)tile_n * NCHUNK * TILE_BYTES;

    const uint32_t cp_off = (uint32_t)tid * 16;

    // ldmatrix lane maps (verified rounds 4-6)
    const uint32_t sx   = (uint32_t)((lane & 7) << 4);
    const uint32_t a_r  = (uint32_t)(((lane >> 3) & 1) * 8 + (lane & 7));
    const uint32_t a_cg = (uint32_t)(lane >> 4);
    const uint32_t b_r  = (uint32_t)(((lane >> 4) & 1) * 8 + (lane & 7));
    const uint32_t b_cg = (uint32_t)((lane >> 3) & 1);

    float acc[2][8][4];
    #pragma unroll
    for (int i = 0; i < 2; i++)
        #pragma unroll
        for (int j = 0; j < 8; j++)
            #pragma unroll
            for (int q = 0; q < 4; q++) acc[i][j][q] = 0.0f;

    auto load_stage = [&](int s, int c) {
        uint32_t st = sb + (uint32_t)s * STAGE_BYTES;
        size_t ko = (size_t)c * TILE_BYTES;
        #pragma unroll
        for (int q = 0; q < 4; q++) {
            uint32_t o = cp_off + (uint32_t)q * 4096;
            cp16(st +         o, A + a0 + ko + o);
            cp16(st + 16384 + o, B + b0 + ko + o);
        }
        CP_COMMIT();
    };

    #pragma unroll
    for (int s = 0; s < NSTAGE; s++) load_stage(s, s);

    for (int c = 0; c < NCHUNK; c++) {
        if (c < NCHUNK - 2)       CP_WAIT(2);
        else if (c == NCHUNK - 2) CP_WAIT(1);
        else                      CP_WAIT(0);
        __syncthreads();

        uint32_t st = sb + (uint32_t)(c % NSTAGE) * STAGE_BYTES;
        uint32_t sA = st, sB = st + 16384;

        #pragma unroll
        for (int ks = 0; ks < 4; ks++) {
            uint32_t a[2][4];
            #pragma unroll
            for (int i = 0; i < 2; i++) {
                uint32_t row = (uint32_t)(wm * 32 + i * 16) + a_r;
                uint32_t cgo = (((uint32_t)(ks * 2) + a_cg) * 16) ^ sx;
                ldsm_x4(a[i], sA + row * 128 + cgo);
            }
            #pragma unroll
            for (int g = 0; g < 4; g++) {
                uint32_t b[4];
                uint32_t row = (uint32_t)(wn * 64 + g * 16) + b_r;
                uint32_t cgo = (((uint32_t)(ks * 2) + b_cg) * 16) ^ sx;
                ldsm_x4(b, sB + row * 128 + cgo);
                #pragma unroll
                for (int i = 0; i < 2; i++) {
                    mma_f16(acc[i][g * 2 + 0], a[i], &b[0]);
                    mma_f16(acc[i][g * 2 + 1], a[i], &b[2]);
                }
            }
        }
        __syncthreads();

        if (c + NSTAGE < NCHUNK) load_stage(c % NSTAGE, c + NSTAGE);
    }

    // ---- epilogue ----
    const int g4 = lane >> 2, t4 = lane & 3;
    if (OUT_F16) {
        // fp16 tiled+swizzled output (qkv buffers)
        uint8_t* C = (uint8_t*)Cout;
        const int nchunks = N >> 6;
        const int chunk = tile_n * 2 + wn;
        uint8_t* tb = C + (size_t)(tile_m * nchunks + chunk) * TILE_BYTES;
        #pragma unroll
        for (int i = 0; i < 2; i++) {
            int rl = wm * 32 + i * 16 + g4;        // and rl+8; (rl+8)&7 == rl&7
            uint32_t sw = (uint32_t)((rl & 7) << 4);
            #pragma unroll
            for (int j = 0; j < 8; j++) {
                int colg = tile_n * 128 + wn * 64 + j * 8 + t4 * 2;
                float bx = bias[colg], by = bias[colg + 1];
                __half2 v0 = __floats2half2_rn(acc[i][j][0] + bx, acc[i][j][1] + by);
                __half2 v1 = __floats2half2_rn(acc[i][j][2] + bx, acc[i][j][3] + by);
                uint32_t base = (uint32_t)(j * 16 + t4 * 4);
                *(__half2*)(tb + (((uint32_t)rl * 128 + base) ^ sw))       = v0;
                *(__half2*)(tb + (((uint32_t)(rl + 8) * 128 + base) ^ sw)) = v1;
            }
        }
    } else {
        // fp32 row-major output (final projection)
        float* C = (float*)Cout;
        #pragma unroll
        for (int i = 0; i < 2; i++) {
            int row = tile_m * 128 + wm * 32 + i * 16 + g4;
            #pragma unroll
            for (int j = 0; j < 8; j++) {
                int col = tile_n * 128 + wn * 64 + j * 8 + t4 * 2;
                float bx = bias[col], by = bias[col + 1];
                float2 v0 = make_float2(acc[i][j][0] + bx, acc[i][j][1] + by);
                float2 v1 = make_float2(acc[i][j][2] + bx, acc[i][j][3] + by);
                *(float2*)(C + (size_t)row * N + col)       = v0;
                *(float2*)(C + (size_t)(row + 8) * N + col) = v1;
            }
        }
    }
}

// ---------------------------------------------------------------------------
// Fused head-mixing attention over BOTH qkv buffers: one warp per token.
// Reads fp16 tiled qkv (36 chunks/tile: q=0..11, k=12..23, v=24..35),
// accumulates o_h + o_w in fp32 regs, writes fp16 proj-A tiles (12 chunks).
// Lane owns d-pair (2*lane, 2*lane+1) -> one half2 per (chunk,row).
// ---------------------------------------------------------------------------
__global__ __launch_bounds__(256) void head_attn2(
    const uint8_t* __restrict__ qkvh, const uint8_t* __restrict__ qkvw,
    uint8_t* __restrict__ aout)
{
    const int lane = threadIdx.x & 31;
    const int warp = threadIdx.x >> 5;
    const int tok  = blockIdx.x * 8 + warp;
    const int tile = tok >> 7, r = tok & 127;
    const float scale = 0.125f;

    // swizzled byte offset of this lane's d-pair within a chunk row
    const uint32_t roff =
        ((uint32_t)(r * 128) + (uint32_t)((lane >> 2) * 16 + (lane & 3) * 4))
        ^ (uint32_t)((r & 7) << 4);

    float2 o[HEADS];
    #pragma unroll
    for (int h = 0; h < HEADS; h++) o[h] = make_float2(0.0f, 0.0f);

    #pragma unroll
    for (int buf = 0; buf < 2; buf++) {
        const uint8_t* base = (buf ? qkvw : qkvh)
                            + (size_t)tile * 36 * TILE_BYTES + roff;
        float2 k[HEADS], v[HEADS];
        #pragma unroll
        for (int g = 0; g < HEADS; g++) {
            k[g] = __half22float2(*(const __half2*)(base + (12 + g) * TILE_BYTES));
            v[g] = __half22float2(*(const __half2*)(base + (24 + g) * TILE_BYTES));
        }

        #pragma unroll
        for (int h = 0; h < HEADS; h++) {
            float2 q = __half22float2(*(const __half2*)(base + h * TILE_BYTES));
            q.x *= scale; q.y *= scale;

            float s[HEADS];
            #pragma unroll
            for (int g = 0; g < HEADS; g++)
                s[g] = fmaf(q.x, k[g].x, q.y * k[g].y);

            #pragma unroll
            for (int off = 16; off > 0; off >>= 1)
                #pragma unroll
                for (int g = 0; g < HEADS; g++)
                    s[g] += __shfl_xor_sync(0xffffffffu, s[g], off);

            float m = s[0];
            #pragma unroll
            for (int g = 1; g < HEADS; g++) m = fmaxf(m, s[g]);
            float sum = 0.0f;
            #pragma unroll
            for (int g = 0; g < HEADS; g++) {
                s[g] = __expf(s[g] - m);
                sum += s[g];
            }
            float inv = 1.0f / sum;

            #pragma unroll
            for (int g = 0; g < HEADS; g++) {
                float p = s[g] * inv;
                o[h].x = fmaf(p, v[g].x, o[h].x);
                o[h].y = fmaf(p, v[g].y, o[h].y);
            }
        }
    }

    uint8_t* ob = aout + (size_t)tile * NCHUNK * TILE_BYTES + roff;
    #pragma unroll
    for (int h = 0; h < HEADS; h++)
        *(__half2*)(ob + h * TILE_BYTES) = __floats2half2_rn(o[h].x, o[h].y);
}

// ---------------------------------------------------------------------------
// Launch
// ---------------------------------------------------------------------------
extern "C" void kernel_launch(void* const* d_in, const int* in_sizes, int n_in,
                              void* d_out, int out_size)
{
    const float* x       = (const float*)d_in[0];
    const float* w_qkv_h = (const float*)d_in[1];
    const float* b_qkv_h = (const float*)d_in[2];
    const float* w_qkv_w = (const float*)d_in[3];
    const float* b_qkv_w = (const float*)d_in[4];
    const float* w_proj  = (const float*)d_in[5];
    const float* b_proj  = (const float*)d_in[6];
    float* out = (float*)d_out;

    uint8_t *A, *Bh, *Bw, *Bp, *qh, *qw, *Ao;
    cudaGetSymbolAddress((void**)&A,  g_A);
    cudaGetSymbolAddress((void**)&Bh, g_Bh);
    cudaGetSymbolAddress((void**)&Bw, g_Bw);
    cudaGetSymbolAddress((void**)&Bp, g_Bp);
    cudaGetSymbolAddress((void**)&qh, g_qkvh);
    cudaGetSymbolAddress((void**)&qw, g_qkvw);
    cudaGetSymbolAddress((void**)&Ao, g_Ao);

    const int gemm_smem = NSTAGE * STAGE_BYTES;   // 98304 B
    cudaFuncSetAttribute(gemm_hmma<0>,
                         cudaFuncAttributeMaxDynamicSharedMemorySize, gemm_smem);
    cudaFuncSetAttribute(gemm_hmma<1>,
                         cudaFuncAttributeMaxDynamicSharedMemorySize, gemm_smem);

    dim3 qkv_grid(DIM3 / 128, T_TOK / 128);   // (18, 256)
    dim3 proj_grid(DIM / 128, T_TOK / 128);   // (6, 256)
    const int attn_grid = T_TOK / 8;          // 4096

    // Converts
    conv_a<<<(T_TOK * 96) / 256, 256>>>(x, A);
    conv_b<<<(DIM3 * 96) / 256, 256>>>(w_qkv_h, Bh, DIM3);
    conv_b<<<(DIM3 * 96) / 256, 256>>>(w_qkv_w, Bw, DIM3);
    conv_b<<<(DIM  * 96) / 256, 256>>>(w_proj,  Bp, DIM);

    // Both QKV GEMMs -> fp16 tiled qkv
    gemm_hmma<1><<<qkv_grid, 256, gemm_smem>>>(A, Bh, b_qkv_h, qh, DIM3);
    gemm_hmma<1><<<qkv_grid, 256, gemm_smem>>>(A, Bw, b_qkv_w, qw, DIM3);

    // Fused dual attention -> fp16 proj-A tiles
    head_attn2<<<attn_grid, 256>>>(qh, qw, Ao);

    // Projection -> fp32 output
    gemm_hmma<0><<<proj_grid, 256, gemm_smem>>>(Ao, Bp, b_proj, out, DIM);
}

// round 8
// speedup vs baseline: 7.9847x; 1.3308x over previous
#include <cuda_runtime.h>
#include <cuda_fp16.h>
#include <cstdint>

// Problem constants
#define T_TOK   32768        // 8*64*64 tokens
#define DIM     768
#define DIM3    2304
#define HEADS   12
#define HD      64
#define NCHUNK  12           // 768 / 64 (K chunks per tile row)
#define TILE_BYTES 16384     // 128 rows x 64 fp16 x 2B
#define STAGE_BYTES 32768    // A tile + B tile
#define NSTAGE  3

// Scratch (fp16 tiled/swizzled)
__device__ uint8_t g_A  [(size_t)(T_TOK/128) * NCHUNK * TILE_BYTES];  // x tiles, 50MB
__device__ uint8_t g_Bh [(size_t)(DIM3/128) * NCHUNK * TILE_BYTES];   // 3.4MB
__device__ uint8_t g_Bw [(size_t)(DIM3/128) * NCHUNK * TILE_BYTES];
__device__ uint8_t g_Bp [(size_t)(DIM/128) * NCHUNK * TILE_BYTES];    // 1.2MB
__device__ uint8_t g_qkvh[(size_t)(T_TOK/128) * 36 * TILE_BYTES];     // 151MB
__device__ uint8_t g_qkvw[(size_t)(T_TOK/128) * 36 * TILE_BYTES];     // 151MB
__device__ uint8_t g_Ao [(size_t)(T_TOK/128) * NCHUNK * TILE_BYTES];  // attn out, 50MB

// ---------------------------------------------------------------------------
// PTX helpers (base-target only: ldmatrix / mma.sync / cp.async)
// ---------------------------------------------------------------------------
__device__ __forceinline__ uint32_t smem_u32(const void* p) {
    uint32_t a;
    asm("{ .reg .u64 t; cvta.to.shared.u64 t, %1; cvt.u32.u64 %0, t; }"
        : "=r"(a) : "l"(p));
    return a;
}

__device__ __forceinline__ void ldsm_x4(uint32_t* r, uint32_t addr) {
    asm volatile("ldmatrix.sync.aligned.m8n8.x4.shared.b16 {%0,%1,%2,%3}, [%4];"
                 : "=r"(r[0]), "=r"(r[1]), "=r"(r[2]), "=r"(r[3]) : "r"(addr));
}

__device__ __forceinline__ void ldsm_x4t(uint32_t* r, uint32_t addr) {
    asm volatile("ldmatrix.sync.aligned.m8n8.x4.trans.shared.b16 {%0,%1,%2,%3}, [%4];"
                 : "=r"(r[0]), "=r"(r[1]), "=r"(r[2]), "=r"(r[3]) : "r"(addr));
}

__device__ __forceinline__ void mma_f16(float* d, const uint32_t* a, const uint32_t* b) {
    asm volatile(
        "mma.sync.aligned.m16n8k16.row.col.f32.f16.f16.f32 "
        "{%0,%1,%2,%3}, {%4,%5,%6,%7}, {%8,%9}, {%0,%1,%2,%3};"
        : "+f"(d[0]), "+f"(d[1]), "+f"(d[2]), "+f"(d[3])
        : "r"(a[0]), "r"(a[1]), "r"(a[2]), "r"(a[3]), "r"(b[0]), "r"(b[1]));
}

__device__ __forceinline__ void cp16(uint32_t smem, const void* gmem) {
    asm volatile("cp.async.cg.shared.global [%0], [%1], 16;"
                 :: "r"(smem), "l"(gmem) : "memory");
}
#define CP_COMMIT() asm volatile("cp.async.commit_group;" ::: "memory")
#define CP_WAIT(n)  asm volatile("cp.async.wait_group %0;" :: "n"(n) : "memory")

__device__ __forceinline__ uint32_t h2u(float x, float y) {
    __half2 h = __floats2half2_rn(x, y);
    return *(uint32_t*)&h;
}

// ---------------------------------------------------------------------------
// Convert + relayout: fp32 -> fp16, pre-tiled 16KB blocks, SW128-style
// swizzle: off(r, c16) = (r*128 + c16*16) ^ ((r&7)<<4).  Tile = 128 rows x 64 fp16.
// ---------------------------------------------------------------------------
union HF8 { __half h[8]; uint4 u; };

__global__ __launch_bounds__(256) void conv_a(
    const float* __restrict__ in, uint8_t* __restrict__ dst)
{
    int idx = blockIdx.x * 256 + threadIdx.x;       // unit = 8 K-elems
    int m = idx / 96;                               // 96 units per row (768/8)
    int u = idx - m * 96;
    const float* p = in + (size_t)m * DIM + u * 8;
    float4 v0 = *(const float4*)p;
    float4 v1 = *(const float4*)(p + 4);
    float f[8] = {v0.x, v0.y, v0.z, v0.w, v1.x, v1.y, v1.z, v1.w};
    HF8 h;
    #pragma unroll
    for (int i = 0; i < 8; i++) h.h[i] = __float2half_rn(f[i]);
    int mtile = m >> 7, r = m & 127, chunk = u >> 3, c16 = u & 7;
    uint32_t off = (uint32_t)(r * 128 + c16 * 16) ^ (uint32_t)((r & 7) << 4);
    *(uint4*)(dst + (size_t)(mtile * NCHUNK + chunk) * TILE_BYTES + off) = h.u;
}

// B [K=768, N] fp32 -> transposed tiles: tile row = n, cols = k
__global__ __launch_bounds__(256) void conv_b(
    const float* __restrict__ w, uint8_t* __restrict__ dst, int N)
{
    int idx = blockIdx.x * 256 + threadIdx.x;       // n * 96 + u
    int n = idx / 96;
    int u = idx - n * 96;
    int k0 = u * 8;
    HF8 h;
    #pragma unroll
    for (int i = 0; i < 8; i++)
        h.h[i] = __float2half_rn(w[(size_t)(k0 + i) * N + n]);
    int ntile = n >> 7, r = n & 127, chunk = u >> 3, c16 = u & 7;
    uint32_t off = (uint32_t)(r * 128 + c16 * 16) ^ (uint32_t)((r & 7) << 4);
    *(uint4*)(dst + (size_t)(ntile * NCHUNK + chunk) * TILE_BYTES + off) = h.u;
}

// ---------------------------------------------------------------------------
// HMMA GEMM core (verified rounds 4-7): C = A @ B^T + bias
// 256 threads = 8 warps in 4(M) x 2(N); warp tile 32 x 64; 3-stage cp.async.
// OUT_F16=0: fp32 row-major. OUT_F16=1: fp16 tiled+swizzled.
// ---------------------------------------------------------------------------
template <int OUT_F16>
__global__ __launch_bounds__(256, 2) void gemm_hmma(
    const uint8_t* __restrict__ A, const uint8_t* __restrict__ B,
    const float* __restrict__ bias, void* __restrict__ Cout, int N)
{
    extern __shared__ uint8_t smem[];
    const uint32_t sb = smem_u32(smem);

    const int tid  = threadIdx.x;
    const int lane = tid & 31;
    const int wid  = tid >> 5;
    const int wm   = wid >> 1;
    const int wn   = wid & 1;

    const int tile_n = blockIdx.x, tile_m = blockIdx.y;
    const size_t a0 = (size_t)tile_m * NCHUNK * TILE_BYTES;
    const size_t b0 = (size_t)tile_n * NCHUNK * TILE_BYTES;

    const uint32_t cp_off = (uint32_t)tid * 16;

    const uint32_t sx   = (uint32_t)((lane & 7) << 4);
    const uint32_t a_r  = (uint32_t)(((lane >> 3) & 1) * 8 + (lane & 7));
    const uint32_t a_cg = (uint32_t)(lane >> 4);
    const uint32_t b_r  = (uint32_t)(((lane >> 4) & 1) * 8 + (lane & 7));
    const uint32_t b_cg = (uint32_t)((lane >> 3) & 1);

    float acc[2][8][4];
    #pragma unroll
    for (int i = 0; i < 2; i++)
        #pragma unroll
        for (int j = 0; j < 8; j++)
            #pragma unroll
            for (int q = 0; q < 4; q++) acc[i][j][q] = 0.0f;

    auto load_stage = [&](int s, int c) {
        uint32_t st = sb + (uint32_t)s * STAGE_BYTES;
        size_t ko = (size_t)c * TILE_BYTES;
        #pragma unroll
        for (int q = 0; q < 4; q++) {
            uint32_t o = cp_off + (uint32_t)q * 4096;
            cp16(st +         o, A + a0 + ko + o);
            cp16(st + 16384 + o, B + b0 + ko + o);
        }
        CP_COMMIT();
    };

    #pragma unroll
    for (int s = 0; s < NSTAGE; s++) load_stage(s, s);

    for (int c = 0; c < NCHUNK; c++) {
        if (c < NCHUNK - 2)       CP_WAIT(2);
        else if (c == NCHUNK - 2) CP_WAIT(1);
        else                      CP_WAIT(0);
        __syncthreads();

        uint32_t st = sb + (uint32_t)(c % NSTAGE) * STAGE_BYTES;
        uint32_t sA = st, sB = st + 16384;

        #pragma unroll
        for (int ks = 0; ks < 4; ks++) {
            uint32_t a[2][4];
            #pragma unroll
            for (int i = 0; i < 2; i++) {
                uint32_t row = (uint32_t)(wm * 32 + i * 16) + a_r;
                uint32_t cgo = (((uint32_t)(ks * 2) + a_cg) * 16) ^ sx;
                ldsm_x4(a[i], sA + row * 128 + cgo);
            }
            #pragma unroll
            for (int g = 0; g < 4; g++) {
                uint32_t b[4];
                uint32_t row = (uint32_t)(wn * 64 + g * 16) + b_r;
                uint32_t cgo = (((uint32_t)(ks * 2) + b_cg) * 16) ^ sx;
                ldsm_x4(b, sB + row * 128 + cgo);
                #pragma unroll
                for (int i = 0; i < 2; i++) {
                    mma_f16(acc[i][g * 2 + 0], a[i], &b[0]);
                    mma_f16(acc[i][g * 2 + 1], a[i], &b[2]);
                }
            }
        }
        __syncthreads();

        if (c + NSTAGE < NCHUNK) load_stage(c % NSTAGE, c + NSTAGE);
    }

    const int g4 = lane >> 2, t4 = lane & 3;
    if (OUT_F16) {
        uint8_t* C = (uint8_t*)Cout;
        const int nchunks = N >> 6;
        const int chunk = tile_n * 2 + wn;
        uint8_t* tb = C + (size_t)(tile_m * nchunks + chunk) * TILE_BYTES;
        #pragma unroll
        for (int i = 0; i < 2; i++) {
            int rl = wm * 32 + i * 16 + g4;
            uint32_t sw = (uint32_t)((rl & 7) << 4);
            #pragma unroll
            for (int j = 0; j < 8; j++) {
                int colg = tile_n * 128 + wn * 64 + j * 8 + t4 * 2;
                float bx = bias[colg], by = bias[colg + 1];
                __half2 v0 = __floats2half2_rn(acc[i][j][0] + bx, acc[i][j][1] + by);
                __half2 v1 = __floats2half2_rn(acc[i][j][2] + bx, acc[i][j][3] + by);
                uint32_t base = (uint32_t)(j * 16 + t4 * 4);
                *(__half2*)(tb + (((uint32_t)rl * 128 + base) ^ sw))       = v0;
                *(__half2*)(tb + (((uint32_t)(rl + 8) * 128 + base) ^ sw)) = v1;
            }
        }
    } else {
        float* C = (float*)Cout;
        #pragma unroll
        for (int i = 0; i < 2; i++) {
            int row = tile_m * 128 + wm * 32 + i * 16 + g4;
            #pragma unroll
            for (int j = 0; j < 8; j++) {
                int col = tile_n * 128 + wn * 64 + j * 8 + t4 * 2;
                float bx = bias[col], by = bias[col + 1];
                float2 v0 = make_float2(acc[i][j][0] + bx, acc[i][j][1] + by);
                float2 v1 = make_float2(acc[i][j][2] + bx, acc[i][j][3] + by);
                *(float2*)(C + (size_t)row * N + col)       = v0;
                *(float2*)(C + (size_t)(row + 8) * N + col) = v1;
            }
        }
    }
}

// ---------------------------------------------------------------------------
// MMA-based head attention: one warp per token, heads padded 12->16.
// S[16,16] = Q.K^T via 8 HMMA; quad-level softmax; O = P.V via 8 HMMA.
// Both qkv buffers accumulated into one O; writes fp16 proj-A tiles.
// smem per warp: Q/K/V each 16 rows x 144B (stride 144 -> conflict-free ldsm).
// ---------------------------------------------------------------------------
#define SLAB 6912    // 3 * 16 * 144

__global__ __launch_bounds__(256) void head_attn_mma(
    const uint8_t* __restrict__ qkvh, const uint8_t* __restrict__ qkvw,
    uint8_t* __restrict__ aout)
{
    extern __shared__ uint8_t sm[];
    const int lane = threadIdx.x & 31;
    const int warp = threadIdx.x >> 5;
    const int tok  = blockIdx.x * 8 + warp;
    const int tile = tok >> 7, r = tok & 127;

    const uint32_t sQ = smem_u32(sm) + (uint32_t)warp * SLAB;
    const uint32_t sK = sQ + 2304;
    const uint32_t sV = sQ + 4608;

    // this lane's 4B within the token's 128B gmem row (swizzled)
    const uint32_t roff = (uint32_t)r * 128
        + ((((uint32_t)(lane >> 2)) * 16) ^ (((uint32_t)(r & 7)) << 4))
        + (uint32_t)(lane & 3) * 4;

    // zero V pad rows 12..15 (contiguous 576B since stride == row bytes)
    #pragma unroll
    for (int i = 0; i < 5; i++) {
        int idx = lane + i * 32;
        if (idx < 144)
            asm volatile("st.shared.u32 [%0], %1;" :: "r"(sV + 1728 + idx * 4), "r"(0u));
    }

    // ldmatrix lane->address maps
    const uint32_t mat = (uint32_t)lane >> 3, mrow = (uint32_t)lane & 7;
    const uint32_t qa = sQ + (mrow + (mat & 1) * 8) * 144 + (mat >> 1) * 16;
    const uint32_t kb = sK + (mrow + (mat >> 1) * 8) * 144 + (mat & 1) * 16;
    const uint32_t vb = sV + (mrow + (mat & 1) * 8) * 144 + (mat >> 1) * 16;

    const uint32_t st_dst = sQ + ((uint32_t)lane & 3) * 4 + (((uint32_t)lane >> 2) ? 0 : 0);
    (void)st_dst;

    float o[8][4];
    #pragma unroll
    for (int j = 0; j < 8; j++)
        #pragma unroll
        for (int q = 0; q < 4; q++) o[j][q] = 0.0f;

    const bool mask_t1 = (lane & 3) >= 2;   // tile1 cols 12..15

    #pragma unroll
    for (int buf = 0; buf < 2; buf++) {
        const uint8_t* base = (buf ? qkvw : qkvh)
                            + (size_t)tile * 36 * TILE_BYTES + roff;
        __syncwarp();
        // load 36 chunk-rows (Q:0-11, K:12-23, V:24-35) -> smem rows
        #pragma unroll
        for (int ch = 0; ch < 36; ch++) {
            uint32_t v = *(const uint32_t*)(base + (size_t)ch * TILE_BYTES);
            uint32_t dst = sQ + (uint32_t)(ch / 12) * 2304
                         + (uint32_t)(ch % 12) * 144 + (uint32_t)lane * 4;
            asm volatile("st.shared.u32 [%0], %1;" :: "r"(dst), "r"(v));
        }
        __syncwarp();

        // ---- S = Q.K^T  (2 n8 tiles x 4 k-chunks) ----
        float s0[4] = {0, 0, 0, 0}, s1[4] = {0, 0, 0, 0};
        #pragma unroll
        for (int kc = 0; kc < 4; kc++) {
            uint32_t aq[4], bk[4];
            ldsm_x4(aq, qa + (uint32_t)kc * 32);
            ldsm_x4(bk, kb + (uint32_t)kc * 32);
            mma_f16(s0, aq, &bk[0]);
            mma_f16(s1, aq, &bk[2]);
        }

        // scale + mask pad columns
        #pragma unroll
        for (int q = 0; q < 4; q++) {
            s0[q] *= 0.125f;
            s1[q] = mask_t1 ? -1e30f : s1[q] * 0.125f;
        }

        // quad softmax: rows r (regs 0,1) and r+8 (regs 2,3)
        float mx0 = fmaxf(fmaxf(s0[0], s0[1]), fmaxf(s1[0], s1[1]));
        float mx1 = fmaxf(fmaxf(s0[2], s0[3]), fmaxf(s1[2], s1[3]));
        mx0 = fmaxf(mx0, __shfl_xor_sync(0xffffffffu, mx0, 1));
        mx0 = fmaxf(mx0, __shfl_xor_sync(0xffffffffu, mx0, 2));
        mx1 = fmaxf(mx1, __shfl_xor_sync(0xffffffffu, mx1, 1));
        mx1 = fmaxf(mx1, __shfl_xor_sync(0xffffffffu, mx1, 2));

        s0[0] = __expf(s0[0] - mx0); s0[1] = __expf(s0[1] - mx0);
        s1[0] = __expf(s1[0] - mx0); s1[1] = __expf(s1[1] - mx0);
        s0[2] = __expf(s0[2] - mx1); s0[3] = __expf(s0[3] - mx1);
        s1[2] = __expf(s1[2] - mx1); s1[3] = __expf(s1[3] - mx1);

        float sum0 = s0[0] + s0[1] + s1[0] + s1[1];
        float sum1 = s0[2] + s0[3] + s1[2] + s1[3];
        sum0 += __shfl_xor_sync(0xffffffffu, sum0, 1);
        sum0 += __shfl_xor_sync(0xffffffffu, sum0, 2);
        sum1 += __shfl_xor_sync(0xffffffffu, sum1, 1);
        sum1 += __shfl_xor_sync(0xffffffffu, sum1, 2);
        float inv0 = 1.0f / sum0, inv1 = 1.0f / sum1;

        // P fp16 A-fragments (accumulator layout == A-fragment layout)
        uint32_t pa[4];
        pa[0] = h2u(s0[0] * inv0, s0[1] * inv0);
        pa[1] = h2u(s0[2] * inv1, s0[3] * inv1);
        pa[2] = h2u(s1[0] * inv0, s1[1] * inv0);
        pa[3] = h2u(s1[2] * inv1, s1[3] * inv1);

        // ---- O += P.V  (8 n8 tiles over d=64) ----
        #pragma unroll
        for (int nb = 0; nb < 4; nb++) {
            uint32_t bv[4];
            ldsm_x4t(bv, vb + (uint32_t)nb * 32);
            mma_f16(o[nb * 2 + 0], pa, &bv[0]);
            mma_f16(o[nb * 2 + 1], pa, &bv[2]);
        }
    }

    // ---- stage O (fp16) into Q slab, then coalesced writes ----
    __syncwarp();
    {
        const uint32_t row0 = (uint32_t)(lane >> 2);
        const uint32_t colb = ((uint32_t)(lane & 3)) * 4;   // 2 halves = 4B
        #pragma unroll
        for (int j = 0; j < 8; j++) {
            uint32_t c = (uint32_t)j * 16 + colb;
            uint32_t v0 = h2u(o[j][0], o[j][1]);
            uint32_t v1 = h2u(o[j][2], o[j][3]);
            asm volatile("st.shared.u32 [%0], %1;" :: "r"(sQ + row0 * 144 + c), "r"(v0));
            asm volatile("st.shared.u32 [%0], %1;" :: "r"(sQ + (row0 + 8) * 144 + c), "r"(v1));
        }
    }
    __syncwarp();
    {
        uint8_t* ob = aout + (size_t)tile * NCHUNK * TILE_BYTES + roff;
        #pragma unroll
        for (int h = 0; h < HEADS; h++) {
            uint32_t v;
            asm volatile("ld.shared.u32 %0, [%1];"
                         : "=r"(v) : "r"(sQ + (uint32_t)h * 144 + (uint32_t)lane * 4));
            *(uint32_t*)(ob + (size_t)h * TILE_BYTES) = v;
        }
    }
}

// ---------------------------------------------------------------------------
// Launch
// ---------------------------------------------------------------------------
extern "C" void kernel_launch(void* const* d_in, const int* in_sizes, int n_in,
                              void* d_out, int out_size)
{
    const float* x       = (const float*)d_in[0];
    const float* w_qkv_h = (const float*)d_in[1];
    const float* b_qkv_h = (const float*)d_in[2];
    const float* w_qkv_w = (const float*)d_in[3];
    const float* b_qkv_w = (const float*)d_in[4];
    const float* w_proj  = (const float*)d_in[5];
    const float* b_proj  = (const float*)d_in[6];
    float* out = (float*)d_out;

    uint8_t *A, *Bh, *Bw, *Bp, *qh, *qw, *Ao;
    cudaGetSymbolAddress((void**)&A,  g_A);
    cudaGetSymbolAddress((void**)&Bh, g_Bh);
    cudaGetSymbolAddress((void**)&Bw, g_Bw);
    cudaGetSymbolAddress((void**)&Bp, g_Bp);
    cudaGetSymbolAddress((void**)&qh, g_qkvh);
    cudaGetSymbolAddress((void**)&qw, g_qkvw);
    cudaGetSymbolAddress((void**)&Ao, g_Ao);

    const int gemm_smem = NSTAGE * STAGE_BYTES;   // 98304 B
    cudaFuncSetAttribute(gemm_hmma<0>,
                         cudaFuncAttributeMaxDynamicSharedMemorySize, gemm_smem);
    cudaFuncSetAttribute(gemm_hmma<1>,
                         cudaFuncAttributeMaxDynamicSharedMemorySize, gemm_smem);
    const int attn_smem = 8 * SLAB;               // 55296 B
    cudaFuncSetAttribute(head_attn_mma,
                         cudaFuncAttributeMaxDynamicSharedMemorySize, attn_smem);

    dim3 qkv_grid(DIM3 / 128, T_TOK / 128);   // (18, 256)
    dim3 proj_grid(DIM / 128, T_TOK / 128);   // (6, 256)
    const int attn_grid = T_TOK / 8;          // 4096

    // Converts
    conv_a<<<(T_TOK * 96) / 256, 256>>>(x, A);
    conv_b<<<(DIM3 * 96) / 256, 256>>>(w_qkv_h, Bh, DIM3);
    conv_b<<<(DIM3 * 96) / 256, 256>>>(w_qkv_w, Bw, DIM3);
    conv_b<<<(DIM  * 96) / 256, 256>>>(w_proj,  Bp, DIM);

    // Both QKV GEMMs -> fp16 tiled qkv
    gemm_hmma<1><<<qkv_grid, 256, gemm_smem>>>(A, Bh, b_qkv_h, qh, DIM3);
    gemm_hmma<1><<<qkv_grid, 256, gemm_smem>>>(A, Bw, b_qkv_w, qw, DIM3);

    // Fused dual attention (tensor-core) -> fp16 proj-A tiles
    head_attn_mma<<<attn_grid, 256, attn_smem>>>(qh, qw, Ao);

    // Projection -> fp32 output
    gemm_hmma<0><<<proj_grid, 256, gemm_smem>>>(Ao, Bp, b_proj, out, DIM);
}